// round 9
// baseline (speedup 1.0000x reference)
#include <cuda_runtime.h>
#include <cstdint>

#define B 8192
#define NNODE 64
#define DOBS 16
#define XROW 18
#define XLEN (B * NNODE * XROW)          // 9437184 floats (x region)
#define EPB 630                          // max edge columns per batch
#define ETOT (B * EPB)                   // 5160960 columns

#define SCAT_BLOCKS 1024
#define BPB (B / SCAT_BLOCKS)            // 8 batches per scatter block

__device__ unsigned g_bitmap[(size_t)B * 128];   // 4096 bits per batch
__device__ int g_cnt[B];
__device__ int g_off[B];
__device__ int g_total;

// ---------------------------------------------------------------------------
// Kernel 1: fused x-write + per-batch edge bitmap. 128 thr/block.
// ---------------------------------------------------------------------------
__global__ void __launch_bounds__(128) build_edges_x(const float* __restrict__ obs,
                                                     const float* __restrict__ ego,
                                                     const float* __restrict__ other,
                                                     float* __restrict__ out) {
    int b = blockIdx.x;
    int t = threadIdx.x;              // 0..127
    int lane = t & 31, w = t >> 5;

    __shared__ float sx[64], sy[64];
    __shared__ unsigned long long skey[64];
    __shared__ int spart[128];
    __shared__ int sord[64];
    __shared__ unsigned sbits[5][2];
    __shared__ unsigned bitmap[128];       // 4096 bits: key = u*64 + v
    __shared__ int warpsum[4];

    const float4* src4 = (const float4*)(obs + (size_t)b * NNODE * DOBS);
    float* xout = out + (size_t)b * NNODE * XROW;

    float4 fa = src4[t];
    float4 fb = src4[t + 128];
    bitmap[t] = 0u;

    // extract x,y columns (row n starts at float4 index n*4)
    if ((t & 3) == 0) { sx[t >> 2] = fa.x; sy[t >> 2] = fa.y; }
    { int i = t + 128; if ((i & 3) == 0) { sx[i >> 2] = fb.x; sy[i >> 2] = fb.y; } }

    // write obs part of x directly: float4 i -> out row n=i>>2, cols 4(i&3)..+3
    {
        int n = t >> 2, q = t & 3;
        float2* p = (float2*)(xout + n * XROW + q * 4);
        p[0] = make_float2(fa.x, fa.y);
        p[1] = make_float2(fa.z, fa.w);
    }
    {
        int i = t + 128;
        int n = i >> 2, q = i & 3;
        float2* p = (float2*)(xout + n * XROW + q * 4);
        p[0] = make_float2(fb.x, fb.y);
        p[1] = make_float2(fb.z, fb.w);
    }
    // init columns 16,17
    if (t < 64) {
        float2 iv = (t == 0) ? make_float2(ego[0], ego[1])
                             : make_float2(other[0], other[1]);
        *(float2*)(xout + t * XROW + DOBS) = iv;
    }
    __syncthreads();   // sx/sy fully written

    // sortable key: x in [0,1) so float bits preserve order; tie-break by index
    if (t < 64) {
        skey[t] = (((unsigned long long)__float_as_uint(sx[t])) << 6) | (unsigned)t;
    }
    __syncthreads();

    // --- stable rank by x: 128 threads, 32 u64 compares each ---
    {
        int node = t & 63;
        int jbase = (t >> 6) * 32;
        unsigned long long ki = skey[node];
        int r = 0;
#pragma unroll
        for (int jj = 0; jj < 32; jj++) {
            r += (skey[jbase + jj] < ki);
        }
        spart[t] = r;
    }
    __syncthreads();
    if (t < 64) sord[spart[t] + spart[t + 64]] = t;
    __syncthreads();

    // --- lane masks + chain edges into bitmap ---
    bool mm[5];
    int node = 0;
    if (t < 64) {
        node = sord[t];               // node at sorted position t
        float ys = sy[node];
        const float T1 = (float)(1.0 / 3.0);
        const float T2 = (float)(2.0 / 3.0);
        bool f0 = (ys <= T1) && (ys > 0.0f);
        bool f1 = (ys > T1) && (ys <= T2);
        bool f2 = (ys >= T2) && (ys < 1.0f);
        mm[0] = f0; mm[1] = f1; mm[2] = f2; mm[3] = f0 || f1; mm[4] = f1 || f2;
#pragma unroll
        for (int m = 0; m < 5; m++) {
            unsigned bal = __ballot_sync(0xffffffffu, mm[m]);
            if (lane == 0) sbits[m][w] = bal;
        }
    }
    __syncthreads();

    if (t < 64) {
#pragma unroll
        for (int m = 0; m < 5; m++) {
            if (mm[m] && t < 63) {
                unsigned long long bits =
                    ((unsigned long long)sbits[m][1] << 32) | (unsigned long long)sbits[m][0];
                unsigned long long rest = bits >> (t + 1);
                if (rest) {
                    int nk = t + 1 + (__ffsll((long long)rest) - 1);
                    int v = sord[nk];
                    int k1 = node * 64 + v;
                    int k2 = v * 64 + node;
                    atomicOr(&bitmap[k1 >> 5], 1u << (k1 & 31));
                    atomicOr(&bitmap[k2 >> 5], 1u << (k2 & 31));
                }
            }
        }
    }
    __syncthreads();

    // --- ship bitmap to global (coalesced) + block reduce for count ---
    unsigned wv = bitmap[t];
    g_bitmap[(size_t)b * 128 + t] = wv;
    int c = __popc(wv);
#pragma unroll
    for (int d = 16; d; d >>= 1) c += __shfl_down_sync(0xffffffffu, c, d);
    if (lane == 0) warpsum[w] = c;
    __syncthreads();
    if (t == 0) g_cnt[b] = warpsum[0] + warpsum[1] + warpsum[2] + warpsum[3];
}

// ---------------------------------------------------------------------------
// Kernel 2: exclusive scan of g_cnt[8192] -> g_off, + g_total
// ---------------------------------------------------------------------------
__global__ void __launch_bounds__(1024) scan_counts() {
    int t = threadIdx.x;
    int lane = t & 31, wid = t >> 5;
    __shared__ int wsum[32];

    int base = t * 8;
    int v[8];
    int s = 0;
#pragma unroll
    for (int i = 0; i < 8; i++) {
        v[i] = s;
        s += g_cnt[base + i];
    }
    int inc = s;
#pragma unroll
    for (int d = 1; d < 32; d <<= 1) {
        int nv = __shfl_up_sync(0xffffffffu, inc, d);
        if (lane >= d) inc += nv;
    }
    if (lane == 31) wsum[wid] = inc;
    __syncthreads();
    if (wid == 0) {
        int wv = wsum[lane];
        int winc = wv;
#pragma unroll
        for (int d = 1; d < 32; d <<= 1) {
            int nv = __shfl_up_sync(0xffffffffu, winc, d);
            if (lane >= d) winc += nv;
        }
        wsum[lane] = winc - wv;   // exclusive warp offsets
    }
    __syncthreads();
    int excl = inc - s + wsum[wid];
#pragma unroll
    for (int i = 0; i < 8; i++) g_off[base + i] = excl + v[i];
    if (t == 1023) g_total = excl + s;
}

// ---------------------------------------------------------------------------
// Kernel 3: decode bitmaps -> edges, + pad. 1024 blocks x 256 threads.
// Each 128-thread half handles one batch; 4 iterations => 8 batches/block.
// ---------------------------------------------------------------------------
__global__ void __launch_bounds__(256) scatter_pad(float* __restrict__ out) {
    int t = threadIdx.x;
    int half = t >> 7;            // 0 or 1
    int u = t & 127;              // thread within half
    int lane = t & 31;
    int w = (t >> 5) & 3;         // warp within half

    __shared__ int hsum[2][2][4]; // [parity][half][warp]

    float* src_out = out + XLEN;
    float* dst_out = out + XLEN + ETOT;

#pragma unroll
    for (int it = 0; it < 4; it++) {
        int b = blockIdx.x * BPB + it * 2 + half;
        unsigned wv = g_bitmap[(size_t)b * 128 + u];
        int off = g_off[b];
        int c = __popc(wv);
        int inc = c;
#pragma unroll
        for (int d = 1; d < 32; d <<= 1) {
            int nv = __shfl_up_sync(0xffffffffu, inc, d);
            if (lane >= d) inc += nv;
        }
        if (lane == 31) hsum[it & 1][half][w] = inc;
        __syncthreads();
        int wpre = 0;
#pragma unroll
        for (int j = 0; j < 4; j++) wpre += (j < w) ? hsum[it & 1][half][j] : 0;
        int pos = off + inc - c + wpre;
        int nb = b * NNODE;
        int kbase = u * 32;
        while (wv) {
            int bit = __ffs(wv) - 1;
            wv &= (wv - 1);
            int k = kbase + bit;
            src_out[pos] = (float)(nb + (k >> 6));
            dst_out[pos] = (float)(nb + (k & 63));
            pos++;
        }
    }

    // pad region [T, ETOT): contiguous run per block
    int T = g_total;
    int P = ETOT - T;
    int chunk = (P + SCAT_BLOCKS - 1) / SCAT_BLOCKS;
    int start = T + blockIdx.x * chunk;
    int end = start + chunk;
    if (end > ETOT) end = ETOT;
    for (int i = start + t; i < end; i += 256) {
        src_out[i] = -1.0f;
        dst_out[i] = -1.0f;
    }
}

// ---------------------------------------------------------------------------
extern "C" void kernel_launch(void* const* d_in, const int* in_sizes, int n_in,
                              void* d_out, int out_size) {
    const float* obs = (const float*)d_in[0];
    const float* ego = (const float*)d_in[1];
    const float* other = (const float*)d_in[2];
    float* out = (float*)d_out;

    build_edges_x<<<B, 128>>>(obs, ego, other, out);
    scan_counts<<<1, 1024>>>();
    scatter_pad<<<SCAT_BLOCKS, 256>>>(out);
}

// round 10
// speedup vs baseline: 1.2219x; 1.2219x over previous
#include <cuda_runtime.h>
#include <cstdint>

#define B 8192
#define NNODE 64
#define DOBS 16
#define XROW 18
#define XLEN (B * NNODE * XROW)          // 9437184 floats (x region)
#define EPB 630                          // max edge columns per batch
#define ETOT (B * EPB)                   // 5160960 columns
#define KEY_STRIDE 640

#define SCAT_BLOCKS 1024
#define BPB (B / SCAT_BLOCKS)            // 8 batches per scatter block

__device__ unsigned short g_keys[(size_t)B * KEY_STRIDE];
__device__ int g_cnt[B];

// ---------------------------------------------------------------------------
// Kernel 1: fused x-write + per-batch edge keys. 128 thr/block. (R8 version)
// ---------------------------------------------------------------------------
__global__ void __launch_bounds__(128) build_edges_x(const float* __restrict__ obs,
                                                     const float* __restrict__ ego,
                                                     const float* __restrict__ other,
                                                     float* __restrict__ out) {
    int b = blockIdx.x;
    int t = threadIdx.x;              // 0..127
    int lane = t & 31, w = t >> 5;

    __shared__ float sx[64], sy[64];
    __shared__ unsigned long long skey[64];
    __shared__ int spart[128];
    __shared__ int sord[64];
    __shared__ unsigned sbits[5][2];
    __shared__ unsigned bitmap[128];       // 4096 bits: key = u*64 + v
    __shared__ int warpsum[4];

    const float4* src4 = (const float4*)(obs + (size_t)b * NNODE * DOBS);
    float* xout = out + (size_t)b * NNODE * XROW;

    float4 fa = src4[t];
    float4 fb = src4[t + 128];
    bitmap[t] = 0u;

    // extract x,y columns (row n starts at float4 index n*4)
    if ((t & 3) == 0) { sx[t >> 2] = fa.x; sy[t >> 2] = fa.y; }
    { int i = t + 128; if ((i & 3) == 0) { sx[i >> 2] = fb.x; sy[i >> 2] = fb.y; } }

    // write obs part of x directly: float4 i -> out row n=i>>2, cols 4(i&3)..+3
    {
        int n = t >> 2, q = t & 3;
        float2* p = (float2*)(xout + n * XROW + q * 4);
        p[0] = make_float2(fa.x, fa.y);
        p[1] = make_float2(fa.z, fa.w);
    }
    {
        int i = t + 128;
        int n = i >> 2, q = i & 3;
        float2* p = (float2*)(xout + n * XROW + q * 4);
        p[0] = make_float2(fb.x, fb.y);
        p[1] = make_float2(fb.z, fb.w);
    }
    // init columns 16,17
    if (t < 64) {
        float2 iv = (t == 0) ? make_float2(ego[0], ego[1])
                             : make_float2(other[0], other[1]);
        *(float2*)(xout + t * XROW + DOBS) = iv;
    }
    __syncthreads();   // sx/sy fully written

    // sortable key: x in [0,1) so float bits preserve order; tie-break by index
    if (t < 64) {
        skey[t] = (((unsigned long long)__float_as_uint(sx[t])) << 6) | (unsigned)t;
    }
    __syncthreads();

    // --- stable rank by x: 128 threads, 32 u64 compares each ---
    {
        int node = t & 63;
        int jbase = (t >> 6) * 32;
        unsigned long long ki = skey[node];
        int r = 0;
#pragma unroll
        for (int jj = 0; jj < 32; jj++) {
            r += (skey[jbase + jj] < ki);
        }
        spart[t] = r;
    }
    __syncthreads();
    if (t < 64) sord[spart[t] + spart[t + 64]] = t;
    __syncthreads();

    // --- lane masks + chain edges into bitmap ---
    bool mm[5];
    int node = 0;
    if (t < 64) {
        node = sord[t];               // node at sorted position t
        float ys = sy[node];
        const float T1 = (float)(1.0 / 3.0);
        const float T2 = (float)(2.0 / 3.0);
        bool f0 = (ys <= T1) && (ys > 0.0f);
        bool f1 = (ys > T1) && (ys <= T2);
        bool f2 = (ys >= T2) && (ys < 1.0f);
        mm[0] = f0; mm[1] = f1; mm[2] = f2; mm[3] = f0 || f1; mm[4] = f1 || f2;
#pragma unroll
        for (int m = 0; m < 5; m++) {
            unsigned bal = __ballot_sync(0xffffffffu, mm[m]);
            if (lane == 0) sbits[m][w] = bal;
        }
    }
    __syncthreads();

    if (t < 64) {
#pragma unroll
        for (int m = 0; m < 5; m++) {
            if (mm[m] && t < 63) {
                unsigned long long bits =
                    ((unsigned long long)sbits[m][1] << 32) | (unsigned long long)sbits[m][0];
                unsigned long long rest = bits >> (t + 1);
                if (rest) {
                    int nk = t + 1 + (__ffsll((long long)rest) - 1);
                    int v = sord[nk];
                    int k1 = node * 64 + v;
                    int k2 = v * 64 + node;
                    atomicOr(&bitmap[k1 >> 5], 1u << (k1 & 31));
                    atomicOr(&bitmap[k2 >> 5], 1u << (k2 & 31));
                }
            }
        }
    }
    __syncthreads();

    // --- compact: each of 128 threads owns one 32-bit bitmap word ---
    unsigned wv = bitmap[t];
    int c = __popc(wv);
    int inc = c;
#pragma unroll
    for (int d = 1; d < 32; d <<= 1) {
        int nv = __shfl_up_sync(0xffffffffu, inc, d);
        if (lane >= d) inc += nv;
    }
    if (lane == 31) warpsum[w] = inc;
    __syncthreads();
    int wpre = 0;
#pragma unroll
    for (int j = 0; j < 4; j++) wpre += (j < w) ? warpsum[j] : 0;
    int excl = inc - c + wpre;
    if (t == 0) g_cnt[b] = warpsum[0] + warpsum[1] + warpsum[2] + warpsum[3];

    unsigned short* kb = g_keys + (size_t)b * KEY_STRIDE;
    int pos = excl;
    int kbase = t * 32;
    while (wv) {
        int bit = __ffs(wv) - 1;
        wv &= (wv - 1);
        kb[pos++] = (unsigned short)(kbase + bit);
    }
}

// ---------------------------------------------------------------------------
// Kernel 2: scatter with fused prefix computation.
// 1024 blocks x 256 threads; each block sums all counts itself.
// ---------------------------------------------------------------------------
__global__ void __launch_bounds__(256) scatter_pad(float* __restrict__ out) {
    int t = threadIdx.x;
    int lane = t & 31, w = t >> 5;
    int b0 = blockIdx.x * BPB;            // multiple of 8 -> int4-aligned

    __shared__ int red_b[8], red_t[8];
    __shared__ int soff[BPB + 1];

    // --- fused scan: sum counts before b0, and total ---
    const int4* c4 = (const int4*)g_cnt;
    int s_before = 0, s_total = 0;
#pragma unroll
    for (int i = t; i < B / 4; i += 256) {
        int4 v = c4[i];
        int sum = v.x + v.y + v.z + v.w;
        s_total += sum;
        if (i * 4 < b0) s_before += sum;   // no partial groups (b0 % 4 == 0)
    }
#pragma unroll
    for (int d = 16; d; d >>= 1) {
        s_before += __shfl_down_sync(0xffffffffu, s_before, d);
        s_total  += __shfl_down_sync(0xffffffffu, s_total, d);
    }
    if (lane == 0) { red_b[w] = s_before; red_t[w] = s_total; }
    __syncthreads();
    if (t == 0) {
        int sb = 0, stt = 0;
#pragma unroll
        for (int j = 0; j < 8; j++) { sb += red_b[j]; stt += red_t[j]; }
        // local prefix over this block's 8 batches
        int acc = sb;
#pragma unroll
        for (int k = 0; k < BPB; k++) { soff[k] = acc; acc += g_cnt[b0 + k]; }
        soff[BPB] = stt;   // reuse slot: total
    }
    __syncthreads();

    float* src_out = out + XLEN;
    float* dst_out = out + XLEN + ETOT;

#pragma unroll
    for (int bb = 0; bb < BPB; bb++) {
        int b = b0 + bb;
        int cnt = g_cnt[b];
        int off = soff[bb];
        const unsigned short* kb = g_keys + (size_t)b * KEY_STRIDE;
        int nb = b * NNODE;
        for (int i = t; i < cnt; i += 256) {
            int k = kb[i];
            src_out[off + i] = (float)(nb + (k >> 6));
            dst_out[off + i] = (float)(nb + (k & 63));
        }
    }

    // pad region [T, ETOT): contiguous run per block
    int T = soff[BPB];
    int P = ETOT - T;
    int chunk = (P + SCAT_BLOCKS - 1) / SCAT_BLOCKS;
    int start = T + blockIdx.x * chunk;
    int end = start + chunk;
    if (end > ETOT) end = ETOT;
    for (int i = start + t; i < end; i += 256) {
        src_out[i] = -1.0f;
        dst_out[i] = -1.0f;
    }
}

// ---------------------------------------------------------------------------
extern "C" void kernel_launch(void* const* d_in, const int* in_sizes, int n_in,
                              void* d_out, int out_size) {
    const float* obs = (const float*)d_in[0];
    const float* ego = (const float*)d_in[1];
    const float* other = (const float*)d_in[2];
    float* out = (float*)d_out;

    build_edges_x<<<B, 128>>>(obs, ego, other, out);
    scatter_pad<<<SCAT_BLOCKS, 256>>>(out);
}

// round 12
// speedup vs baseline: 1.2230x; 1.0009x over previous
#include <cuda_runtime.h>
#include <cstdint>

#define B 8192
#define NNODE 64
#define DOBS 16
#define XROW 18
#define XLEN (B * NNODE * XROW)          // 9437184 floats (x region)
#define EPB 630                          // max edge columns per batch
#define ETOT (B * EPB)                   // 5160960 columns
#define KEY_STRIDE 640

#define SCAT_BLOCKS 512
#define BPB (B / SCAT_BLOCKS)            // 16 batches per scatter block

__device__ unsigned short g_keys[(size_t)B * KEY_STRIDE];
__device__ int g_cnt[B];

// ---------------------------------------------------------------------------
// Kernel 1: fused x-write + per-batch edge keys. 128 thr/block.
// ---------------------------------------------------------------------------
__global__ void __launch_bounds__(128) build_edges_x(const float* __restrict__ obs,
                                                     const float* __restrict__ ego,
                                                     const float* __restrict__ other,
                                                     float* __restrict__ out) {
    int b = blockIdx.x;
    int t = threadIdx.x;              // 0..127
    int lane = t & 31, w = t >> 5;

    __shared__ float sx[64], sy[64];
    __shared__ unsigned long long skey[64];
    __shared__ int spart[128];
    __shared__ int sord[64];
    __shared__ unsigned sbits[5][2];
    __shared__ unsigned bitmap[128];       // 4096 bits: key = u*64 + v
    __shared__ int warpsum[4];

    const float4* src4 = (const float4*)(obs + (size_t)b * NNODE * DOBS);
    float* xout = out + (size_t)b * NNODE * XROW;

    float4 fa = src4[t];
    float4 fb = src4[t + 128];
    bitmap[t] = 0u;

    // extract x,y columns (row n starts at float4 index n*4)
    if ((t & 3) == 0) { sx[t >> 2] = fa.x; sy[t >> 2] = fa.y; }
    { int i = t + 128; if ((i & 3) == 0) { sx[i >> 2] = fb.x; sy[i >> 2] = fb.y; } }

    // write obs part of x directly: float4 i -> out row n=i>>2, cols 4(i&3)..+3
    {
        int n = t >> 2, q = t & 3;
        float2* p = (float2*)(xout + n * XROW + q * 4);
        p[0] = make_float2(fa.x, fa.y);
        p[1] = make_float2(fa.z, fa.w);
    }
    {
        int i = t + 128;
        int n = i >> 2, q = i & 3;
        float2* p = (float2*)(xout + n * XROW + q * 4);
        p[0] = make_float2(fb.x, fb.y);
        p[1] = make_float2(fb.z, fb.w);
    }
    // init columns 16,17
    if (t < 64) {
        float2 iv = (t == 0) ? make_float2(ego[0], ego[1])
                             : make_float2(other[0], other[1]);
        *(float2*)(xout + t * XROW + DOBS) = iv;
    }
    __syncthreads();   // sx/sy fully written

    // sortable key: x in [0,1) so float bits preserve order; tie-break by index
    if (t < 64) {
        skey[t] = (((unsigned long long)__float_as_uint(sx[t])) << 6) | (unsigned)t;
    }
    __syncthreads();

    // --- stable rank by x: 128 threads, 32 u64 compares each ---
    {
        int node = t & 63;
        int jbase = (t >> 6) * 32;
        unsigned long long ki = skey[node];
        int r = 0;
#pragma unroll
        for (int jj = 0; jj < 32; jj++) {
            r += (skey[jbase + jj] < ki);
        }
        spart[t] = r;
    }
    __syncthreads();
    if (t < 64) sord[spart[t] + spart[t + 64]] = t;
    __syncthreads();

    // --- lane masks + chain edges into bitmap ---
    bool mm[5];
    int node = 0;
    if (t < 64) {
        node = sord[t];               // node at sorted position t
        float ys = sy[node];
        const float T1 = (float)(1.0 / 3.0);
        const float T2 = (float)(2.0 / 3.0);
        bool f0 = (ys <= T1) && (ys > 0.0f);
        bool f1 = (ys > T1) && (ys <= T2);
        bool f2 = (ys >= T2) && (ys < 1.0f);
        mm[0] = f0; mm[1] = f1; mm[2] = f2; mm[3] = f0 || f1; mm[4] = f1 || f2;
#pragma unroll
        for (int m = 0; m < 5; m++) {
            unsigned bal = __ballot_sync(0xffffffffu, mm[m]);
            if (lane == 0) sbits[m][w] = bal;
        }
    }
    __syncthreads();

    if (t < 64) {
#pragma unroll
        for (int m = 0; m < 5; m++) {
            if (mm[m] && t < 63) {
                unsigned long long bits =
                    ((unsigned long long)sbits[m][1] << 32) | (unsigned long long)sbits[m][0];
                unsigned long long rest = bits >> (t + 1);
                if (rest) {
                    int nk = t + 1 + (__ffsll((long long)rest) - 1);
                    int v = sord[nk];
                    int k1 = node * 64 + v;
                    int k2 = v * 64 + node;
                    atomicOr(&bitmap[k1 >> 5], 1u << (k1 & 31));
                    atomicOr(&bitmap[k2 >> 5], 1u << (k2 & 31));
                }
            }
        }
    }
    __syncthreads();

    // --- compact: each of 128 threads owns one 32-bit bitmap word ---
    unsigned wv = bitmap[t];
    int c = __popc(wv);
    int inc = c;
#pragma unroll
    for (int d = 1; d < 32; d <<= 1) {
        int nv = __shfl_up_sync(0xffffffffu, inc, d);
        if (lane >= d) inc += nv;
    }
    if (lane == 31) warpsum[w] = inc;
    __syncthreads();
    int wpre = 0;
#pragma unroll
    for (int j = 0; j < 4; j++) wpre += (j < w) ? warpsum[j] : 0;
    int excl = inc - c + wpre;
    if (t == 0) g_cnt[b] = warpsum[0] + warpsum[1] + warpsum[2] + warpsum[3];

    unsigned short* kb = g_keys + (size_t)b * KEY_STRIDE;
    int pos = excl;
    int kbase = t * 32;
    while (wv) {
        int bit = __ffs(wv) - 1;
        wv &= (wv - 1);
        kb[pos++] = (unsigned short)(kbase + bit);
    }
}

// ---------------------------------------------------------------------------
// Kernel 2: scatter with fused prefix. 512 blocks x 256 threads, 16 b/block.
// ---------------------------------------------------------------------------
__global__ void __launch_bounds__(256) scatter_pad(float* __restrict__ out) {
    int t = threadIdx.x;
    int lane = t & 31, w = t >> 5;
    int b0 = blockIdx.x * BPB;            // multiple of 16 -> int4-aligned

    __shared__ int red_b[8], red_t[8];
    __shared__ int soff[BPB + 1];

    // --- fused scan: sum counts before b0, and total ---
    const int4* c4 = (const int4*)g_cnt;
    int s_before = 0, s_total = 0;
#pragma unroll
    for (int i = t; i < B / 4; i += 256) {
        int4 v = c4[i];
        int sum = v.x + v.y + v.z + v.w;
        s_total += sum;
        if (i * 4 < b0) s_before += sum;   // no partial groups (b0 % 4 == 0)
    }
#pragma unroll
    for (int d = 16; d; d >>= 1) {
        s_before += __shfl_down_sync(0xffffffffu, s_before, d);
        s_total  += __shfl_down_sync(0xffffffffu, s_total, d);
    }
    if (lane == 0) { red_b[w] = s_before; red_t[w] = s_total; }
    __syncthreads();
    // warp 0, lanes 0..15: parallel local prefix over this block's batches
    if (w == 0) {
        int sb = 0, stt = 0;
#pragma unroll
        for (int j = 0; j < 8; j++) { sb += red_b[j]; stt += red_t[j]; }
        int c = (lane < BPB) ? g_cnt[b0 + lane] : 0;
        int inc = c;
#pragma unroll
        for (int d = 1; d < BPB; d <<= 1) {
            int nv = __shfl_up_sync(0xffffffffu, inc, d);
            if (lane >= d) inc += nv;
        }
        if (lane < BPB) soff[lane] = sb + inc - c;
        if (lane == 0) soff[BPB] = stt;
    }
    __syncthreads();

    float* src_out = out + XLEN;
    float* dst_out = out + XLEN + ETOT;

#pragma unroll
    for (int bb = 0; bb < BPB; bb++) {
        int b = b0 + bb;
        int cnt = g_cnt[b];
        int off = soff[bb];
        const unsigned short* kb = g_keys + (size_t)b * KEY_STRIDE;
        int nb = b * NNODE;
        for (int i = t; i < cnt; i += 256) {
            int k = kb[i];
            src_out[off + i] = (float)(nb + (k >> 6));
            dst_out[off + i] = (float)(nb + (k & 63));
        }
    }

    // pad region [T, ETOT): contiguous run per block, float4 body
    int T = soff[BPB];
    int P = ETOT - T;
    int chunk = (P + SCAT_BLOCKS - 1) / SCAT_BLOCKS;
    int start = T + blockIdx.x * chunk;
    int end = start + chunk;
    if (end > ETOT) end = ETOT;
    if (start < end) {
        int a0 = (start + 3) & ~3;
        int a1 = end & ~3;
        if (a0 > end) a0 = end;          // tiny range fallback
        if (a1 < a0) a1 = a0;
        // scalar head/tail
        if (t < a0 - start) { src_out[start + t] = -1.0f; dst_out[start + t] = -1.0f; }
        if (t < end - a1)  { src_out[a1 + t] = -1.0f;     dst_out[a1 + t] = -1.0f; }
        // vector body
        float4 m1 = make_float4(-1.0f, -1.0f, -1.0f, -1.0f);
        float4* s4 = (float4*)src_out;
        float4* d4 = (float4*)dst_out;
        for (int j = (a0 >> 2) + t; j < (a1 >> 2); j += 256) {
            s4[j] = m1;
            d4[j] = m1;
        }
    }
}

// ---------------------------------------------------------------------------
extern "C" void kernel_launch(void* const* d_in, const int* in_sizes, int n_in,
                              void* d_out, int out_size) {
    const float* obs = (const float*)d_in[0];
    const float* ego = (const float*)d_in[1];
    const float* other = (const float*)d_in[2];
    float* out = (float*)d_out;

    build_edges_x<<<B, 128>>>(obs, ego, other, out);
    scatter_pad<<<SCAT_BLOCKS, 256>>>(out);
}

// round 13
// speedup vs baseline: 1.2884x; 1.0535x over previous
#include <cuda_runtime.h>
#include <cstdint>

#define B 8192
#define NNODE 64
#define DOBS 16
#define XROW 18
#define XLEN (B * NNODE * XROW)          // 9437184 floats (x region)
#define EPB 630                          // max edge columns per batch
#define ETOT (B * EPB)                   // 5160960 columns
#define KEY_STRIDE 640

#define SCAT_BLOCKS 512
#define BPB (B / SCAT_BLOCKS)            // 16 batches per scatter block

__device__ unsigned short g_keys[(size_t)B * KEY_STRIDE];
__device__ int g_cnt[B];

// ---------------------------------------------------------------------------
// Kernel 1: fused x-write + per-batch edge keys. 128 thr/block. (unchanged)
// ---------------------------------------------------------------------------
__global__ void __launch_bounds__(128) build_edges_x(const float* __restrict__ obs,
                                                     const float* __restrict__ ego,
                                                     const float* __restrict__ other,
                                                     float* __restrict__ out) {
    int b = blockIdx.x;
    int t = threadIdx.x;              // 0..127
    int lane = t & 31, w = t >> 5;

    __shared__ float sx[64], sy[64];
    __shared__ unsigned long long skey[64];
    __shared__ int spart[128];
    __shared__ int sord[64];
    __shared__ unsigned sbits[5][2];
    __shared__ unsigned bitmap[128];       // 4096 bits: key = u*64 + v
    __shared__ int warpsum[4];

    const float4* src4 = (const float4*)(obs + (size_t)b * NNODE * DOBS);
    float* xout = out + (size_t)b * NNODE * XROW;

    float4 fa = src4[t];
    float4 fb = src4[t + 128];
    bitmap[t] = 0u;

    // extract x,y columns (row n starts at float4 index n*4)
    if ((t & 3) == 0) { sx[t >> 2] = fa.x; sy[t >> 2] = fa.y; }
    { int i = t + 128; if ((i & 3) == 0) { sx[i >> 2] = fb.x; sy[i >> 2] = fb.y; } }

    // write obs part of x directly: float4 i -> out row n=i>>2, cols 4(i&3)..+3
    {
        int n = t >> 2, q = t & 3;
        float2* p = (float2*)(xout + n * XROW + q * 4);
        p[0] = make_float2(fa.x, fa.y);
        p[1] = make_float2(fa.z, fa.w);
    }
    {
        int i = t + 128;
        int n = i >> 2, q = i & 3;
        float2* p = (float2*)(xout + n * XROW + q * 4);
        p[0] = make_float2(fb.x, fb.y);
        p[1] = make_float2(fb.z, fb.w);
    }
    // init columns 16,17
    if (t < 64) {
        float2 iv = (t == 0) ? make_float2(ego[0], ego[1])
                             : make_float2(other[0], other[1]);
        *(float2*)(xout + t * XROW + DOBS) = iv;
    }
    __syncthreads();   // sx/sy fully written

    // sortable key: x in [0,1) so float bits preserve order; tie-break by index
    if (t < 64) {
        skey[t] = (((unsigned long long)__float_as_uint(sx[t])) << 6) | (unsigned)t;
    }
    __syncthreads();

    // --- stable rank by x: 128 threads, 32 u64 compares each ---
    {
        int node = t & 63;
        int jbase = (t >> 6) * 32;
        unsigned long long ki = skey[node];
        int r = 0;
#pragma unroll
        for (int jj = 0; jj < 32; jj++) {
            r += (skey[jbase + jj] < ki);
        }
        spart[t] = r;
    }
    __syncthreads();
    if (t < 64) sord[spart[t] + spart[t + 64]] = t;
    __syncthreads();

    // --- lane masks + chain edges into bitmap ---
    bool mm[5];
    int node = 0;
    if (t < 64) {
        node = sord[t];               // node at sorted position t
        float ys = sy[node];
        const float T1 = (float)(1.0 / 3.0);
        const float T2 = (float)(2.0 / 3.0);
        bool f0 = (ys <= T1) && (ys > 0.0f);
        bool f1 = (ys > T1) && (ys <= T2);
        bool f2 = (ys >= T2) && (ys < 1.0f);
        mm[0] = f0; mm[1] = f1; mm[2] = f2; mm[3] = f0 || f1; mm[4] = f1 || f2;
#pragma unroll
        for (int m = 0; m < 5; m++) {
            unsigned bal = __ballot_sync(0xffffffffu, mm[m]);
            if (lane == 0) sbits[m][w] = bal;
        }
    }
    __syncthreads();

    if (t < 64) {
#pragma unroll
        for (int m = 0; m < 5; m++) {
            if (mm[m] && t < 63) {
                unsigned long long bits =
                    ((unsigned long long)sbits[m][1] << 32) | (unsigned long long)sbits[m][0];
                unsigned long long rest = bits >> (t + 1);
                if (rest) {
                    int nk = t + 1 + (__ffsll((long long)rest) - 1);
                    int v = sord[nk];
                    int k1 = node * 64 + v;
                    int k2 = v * 64 + node;
                    atomicOr(&bitmap[k1 >> 5], 1u << (k1 & 31));
                    atomicOr(&bitmap[k2 >> 5], 1u << (k2 & 31));
                }
            }
        }
    }
    __syncthreads();

    // --- compact: each of 128 threads owns one 32-bit bitmap word ---
    unsigned wv = bitmap[t];
    int c = __popc(wv);
    int inc = c;
#pragma unroll
    for (int d = 1; d < 32; d <<= 1) {
        int nv = __shfl_up_sync(0xffffffffu, inc, d);
        if (lane >= d) inc += nv;
    }
    if (lane == 31) warpsum[w] = inc;
    __syncthreads();
    int wpre = 0;
#pragma unroll
    for (int j = 0; j < 4; j++) wpre += (j < w) ? warpsum[j] : 0;
    int excl = inc - c + wpre;
    if (t == 0) g_cnt[b] = warpsum[0] + warpsum[1] + warpsum[2] + warpsum[3];

    unsigned short* kb = g_keys + (size_t)b * KEY_STRIDE;
    int pos = excl;
    int kbase = t * 32;
    while (wv) {
        int bit = __ffs(wv) - 1;
        wv &= (wv - 1);
        kb[pos++] = (unsigned short)(kbase + bit);
    }
}

// ---------------------------------------------------------------------------
// Kernel 2: flattened scatter with fused prefix. 512 blocks x 256 threads.
// ---------------------------------------------------------------------------
__global__ void __launch_bounds__(256) scatter_pad(float* __restrict__ out) {
    int t = threadIdx.x;
    int lane = t & 31, w = t >> 5;
    int b0 = blockIdx.x * BPB;            // multiple of 16 -> int4-aligned

    __shared__ int red_b[8], red_t[8];
    __shared__ int cum[BPB + 1];          // local cumulative counts
    __shared__ int sh_sb, sh_tot;

    // --- fused scan: sum counts before b0, and total ---
    const int4* c4 = (const int4*)g_cnt;
    int s_before = 0, s_total = 0;
#pragma unroll
    for (int i = t; i < B / 4; i += 256) {
        int4 v = c4[i];
        int sum = v.x + v.y + v.z + v.w;
        s_total += sum;
        if (i * 4 < b0) s_before += sum;   // no partial groups (b0 % 4 == 0)
    }
#pragma unroll
    for (int d = 16; d; d >>= 1) {
        s_before += __shfl_down_sync(0xffffffffu, s_before, d);
        s_total  += __shfl_down_sync(0xffffffffu, s_total, d);
    }
    if (lane == 0) { red_b[w] = s_before; red_t[w] = s_total; }
    __syncthreads();
    // warp 0: local inclusive scan of this block's 16 counts -> cum[1..16]
    if (w == 0) {
        int sb = 0, stt = 0;
#pragma unroll
        for (int j = 0; j < 8; j++) { sb += red_b[j]; stt += red_t[j]; }
        int c = (lane < BPB) ? g_cnt[b0 + lane] : 0;
        int inc = c;
#pragma unroll
        for (int d = 1; d < BPB; d <<= 1) {
            int nv = __shfl_up_sync(0xffffffffu, inc, d);
            if (lane >= d) inc += nv;
        }
        if (lane < BPB) cum[lane + 1] = inc;
        if (lane == 0) { cum[0] = 0; sh_sb = sb; sh_tot = stt; }
    }
    __syncthreads();

    float* src_out = out + XLEN;
    float* dst_out = out + XLEN + ETOT;

    // --- flat edge loop: contiguous coalesced stores, independent loads ---
    int sb = sh_sb;
    int tot = cum[BPB];
    for (int e = t; e < tot; e += 256) {
        // find bb: largest index with cum[bb] <= e (16 entries, 4-step search)
        int lo = 0;
        if (cum[lo + 8] <= e) lo += 8;
        if (cum[lo + 4] <= e) lo += 4;
        if (cum[lo + 2] <= e) lo += 2;
        if (cum[lo + 1] <= e) lo += 1;
        int i = e - cum[lo];
        int k = g_keys[(size_t)(b0 + lo) * KEY_STRIDE + i];
        int nb = (b0 + lo) * NNODE;
        src_out[sb + e] = (float)(nb + (k >> 6));
        dst_out[sb + e] = (float)(nb + (k & 63));
    }

    // pad region [T, ETOT): contiguous run per block, float4 body
    int T = sh_tot;
    int P = ETOT - T;
    int chunk = (P + SCAT_BLOCKS - 1) / SCAT_BLOCKS;
    int start = T + blockIdx.x * chunk;
    int end = start + chunk;
    if (end > ETOT) end = ETOT;
    if (start < end) {
        int a0 = (start + 3) & ~3;
        int a1 = end & ~3;
        if (a0 > end) a0 = end;          // tiny range fallback
        if (a1 < a0) a1 = a0;
        // scalar head/tail
        if (t < a0 - start) { src_out[start + t] = -1.0f; dst_out[start + t] = -1.0f; }
        if (t < end - a1)  { src_out[a1 + t] = -1.0f;     dst_out[a1 + t] = -1.0f; }
        // vector body
        float4 m1 = make_float4(-1.0f, -1.0f, -1.0f, -1.0f);
        float4* s4 = (float4*)src_out;
        float4* d4 = (float4*)dst_out;
        for (int j = (a0 >> 2) + t; j < (a1 >> 2); j += 256) {
            s4[j] = m1;
            d4[j] = m1;
        }
    }
}

// ---------------------------------------------------------------------------
extern "C" void kernel_launch(void* const* d_in, const int* in_sizes, int n_in,
                              void* d_out, int out_size) {
    const float* obs = (const float*)d_in[0];
    const float* ego = (const float*)d_in[1];
    const float* other = (const float*)d_in[2];
    float* out = (float*)d_out;

    build_edges_x<<<B, 128>>>(obs, ego, other, out);
    scatter_pad<<<SCAT_BLOCKS, 256>>>(out);
}